// round 11
// baseline (speedup 1.0000x reference)
#include <cuda_runtime.h>
#include <cuda_fp16.h>
#include <cstdint>

// ---------------- problem constants ----------------
#define CIN   32
#define COUT  64
#define HO    62
#define WO    62
#define KDIM  288          // (c,g) = 32*9
#define MTOT  65536        // b*h*w pixels
#define MOUT  126          // output rows per CTA
#define NCTA  521

// ---------------- device scratch ----------------
__device__ __align__(16) __half g_B[9 * 64 * KDIM];   // [tap][n][k] fp16

// ---------------- helpers ----------------
__device__ __forceinline__ uint32_t smem_u32(const void* p) {
    uint32_t a;
    asm("{ .reg .u64 t; cvta.to.shared.u64 t, %1; cvt.u32.u64 %0, t; }" : "=r"(a) : "l"(p));
    return a;
}
__device__ __forceinline__ void cp16(uint32_t dst, const void* src) {
    asm volatile("cp.async.cg.shared.global [%0], [%1], 16;" :: "r"(dst), "l"(src));
}
#define CP_COMMIT() asm volatile("cp.async.commit_group;" ::: "memory")
#define CP_WAIT1()  asm volatile("cp.async.wait_group 1;" ::: "memory")

#define LDSM4(r, a)                                                          \
    asm volatile("ldmatrix.sync.aligned.m8n8.x4.shared.b16 {%0,%1,%2,%3}, [%4];" \
        : "=r"((r)[0]), "=r"((r)[1]), "=r"((r)[2]), "=r"((r)[3]) : "r"(a))
#define LDSM2(r, a)                                                          \
    asm volatile("ldmatrix.sync.aligned.m8n8.x2.shared.b16 {%0,%1}, [%2];"   \
        : "=r"((r)[0]), "=r"((r)[1]) : "r"(a))
#define MMA(d, a, b)                                                         \
    asm volatile("mma.sync.aligned.m16n8k16.row.col.f32.f16.f16.f32 "        \
        "{%0,%1,%2,%3}, {%4,%5,%6,%7}, {%8,%9}, {%0,%1,%2,%3};"              \
        : "+f"((d)[0]), "+f"((d)[1]), "+f"((d)[2]), "+f"((d)[3])             \
        : "r"((a)[0]), "r"((a)[1]), "r"((a)[2]), "r"((a)[3]),                \
          "r"((b)[0]), "r"((b)[1]))
#define STH(addr, h)                                                         \
    asm volatile("st.shared.b16 [%0], %1;" :: "r"(addr), "h"(h))

// ---------------- kernel 1: fold weights -> fp16 ----------------
__global__ void fold_kernel(const float* __restrict__ bw,
                            const float* __restrict__ sw,
                            const float* __restrict__ ss) {
    int i = blockIdx.x * blockDim.x + threadIdx.x;    // [tap][n][k]
    if (i >= 9 * 64 * KDIM) return;
    int k = i % KDIM;
    int n = (i / KDIM) & 63;
    int p = i / (KDIM * 64);
    int c = k / 9, g = k % 9;
    int ocp = (n * CIN + c) * 9 + p;
    float val = (g == 0) ? bw[ocp] : sw[ocp * 8 + (g - 1)] * ss[ocp];
    g_B[i] = __float2half(val);
}

// ---------------- kernel 2: fused feature + mma.sync GEMM ----------------
// smem: xs fp32 [32 ch][258 rows] = 33024 B
//       2 x { A[258 rows][48B] = 12384 ; B[9][64][48B] = 27648 } = 80064 B
// total 113088 B/CTA -> 2 CTAs/SM.
#define APITCH 48
#define AROWS  258
#define XPITCH 258
#define XSZ    (CIN * XPITCH * 4)        // 33024
#define BOFF   (AROWS * APITCH)          // 12384
#define BTILE  (64 * APITCH)             // 3072
#define BUFSZ  (BOFF + 9 * BTILE)        // 40032
#define SMEM_TOT (XSZ + 2 * BUFSZ)       // 113088

__global__ void __launch_bounds__(256, 2) gemm_kernel(const float* __restrict__ x,
                                                      float* __restrict__ out) {
    extern __shared__ __align__(16) char smem[];
    float* xs = (float*)smem;
    uint32_t sb = smem_u32(smem);
    const uint32_t buf_base = sb + XSZ;
    const int tid  = threadIdx.x;
    const int lane = tid & 31;
    const int wid  = tid >> 5;
    const int mw = wid & 3;
    const int nw = wid >> 2;
    const int m0 = blockIdx.x * MOUT;

    const char* Bp = (const char*)g_B;

    // ---- prolog: load x slab (32 ch x 258 rows), zero-padded past MTOT ----
    for (int u = tid; u < CIN * 258; u += 256) {
        int c = u / 258, row = u - c * 258;
        int m = m0 + row;
        float v = 0.0f;
        if (m < MTOT)
            v = x[(((size_t)(m >> 12) * CIN + c) << 12) + (m & 4095)];
        xs[c * XPITCH + row] = v;
    }
    __syncthreads();

    // ---- on-the-fly A fill: 16 k-columns of chunk kc into buffer bb ----
    auto fillA = [&](int kc, uint32_t bb) {
        const int k0 = kc * 16;
        const int c_lo = k0 / 9;
#pragma unroll
        for (int it = 0; it < 4; ++it) {
            int e = tid + it * 256;
            if (e >= 3 * 258) break;
            int cc  = e / 258;
            int row = e - cc * 258;
            int c   = c_lo + cc;
            if (c < CIN) {
                int gk   = c * 9;
                int g_lo = (k0 > gk) ? (k0 - gk) : 0;
                int g_hi = k0 + 15 - gk; if (g_hi > 8) g_hi = 8;
                if (g_lo <= g_hi) {
                    float v = xs[c * XPITCH + row];
                    uint32_t base = bb + row * APITCH + (uint32_t)((gk - k0) * 2);
                    if (g_lo == 0) {
                        float si = __fdividef(v, 1.0f + __expf(-v));
                        STH(base, __half_as_ushort(__float2half(si)));
                        g_lo = 1;
                    }
                    // cubic B-spline: 4 nonzero cardinal weights
                    float s  = (v + 2.2f) * 2.5f;
                    float fs = floorf(s);
                    int idx  = (int)fs;
                    float u  = s - fs;
                    float um = 1.0f - u;
                    float u2 = u * u, u3 = u2 * u;
                    const float k6 = 1.0f / 6.0f;
                    float w0 = um * um * um * k6;
                    float w1 = (3.0f * u3 - 6.0f * u2 + 4.0f) * k6;
                    float w2 = (-3.0f * u3 + 3.0f * u2 + 3.0f * u + 1.0f) * k6;
                    float w3 = u3 * k6;
                    int j = (idx >= 0 && idx <= 10) ? (idx - 3) : -100;
                    for (int g = g_lo; g <= g_hi; ++g) {
                        int bi = g - 1;
                        float val = (bi == j)     ? w0
                                  : (bi == j + 1) ? w1
                                  : (bi == j + 2) ? w2
                                  : (bi == j + 3) ? w3 : 0.0f;
                        STH(base + g * 2, __half_as_ushort(__float2half(val)));
                    }
                }
            }
        }
    };

    // ---- B prefetch via cp.async (1152 x 16B per chunk) ----
    auto prefetchB = [&](int kc, uint32_t bb) {
#pragma unroll
        for (int i = 0; i < 5; ++i) {
            int u = tid + i * 256;
            if (u >= 1152) break;
            int tile = u >> 7, row = (u >> 1) & 63, half = u & 1;
            const char* src = Bp + (size_t)(tile * 64 + row) * (KDIM * 2)
                            + kc * 32 + half * 16;
            cp16(bb + BOFF + tile * BTILE + row * APITCH + half * 16, src);
        }
    };

    float acc[2][4][4];
#pragma unroll
    for (int b = 0; b < 2; ++b)
#pragma unroll
        for (int c = 0; c < 4; ++c)
#pragma unroll
            for (int d = 0; d < 4; ++d) acc[b][c][d] = 0.0f;

    const uint32_t a_lane = (uint32_t)((lane & 15) * APITCH + (lane >> 4) * 16);
    const uint32_t b_lane = (uint32_t)((lane & 7) * APITCH + ((lane >> 3) & 1) * 16);

    fillA(0, buf_base);
    prefetchB(0, buf_base);
    CP_COMMIT();

    for (int kc = 0; kc < 18; ++kc) {
        if (kc < 17) {
            uint32_t nb = buf_base + ((kc + 1) & 1) * BUFSZ;
            fillA(kc + 1, nb);
            prefetchB(kc + 1, nb);
        }
        CP_COMMIT();
        CP_WAIT1();
        __syncthreads();

        const uint32_t bb = buf_base + (kc & 1) * BUFSZ;
#pragma unroll
        for (int kh = 0; kh < 3; ++kh)
#pragma unroll
            for (int kw = 0; kw < 3; ++kw) {
                uint32_t ah[2][4];
#pragma unroll
                for (int t2 = 0; t2 < 2; ++t2) {
                    uint32_t ra = bb + (kh * 64 + kw + mw * 32 + t2 * 16) * APITCH + a_lane;
                    LDSM4(ah[t2], ra);
                }
                const int tile = kh * 3 + kw;
#pragma unroll
                for (int nf = 0; nf < 4; ++nf) {
                    uint32_t rb = bb + BOFF + tile * BTILE
                                + (nw * 32 + nf * 8) * APITCH + b_lane;
                    uint32_t bfr[2];
                    LDSM2(bfr, rb);
#pragma unroll
                    for (int t2 = 0; t2 < 2; ++t2)
                        MMA(acc[t2][nf], ah[t2], bfr);
                }
            }
        __syncthreads();
    }

    // ---- epilogue: registers -> gmem directly ----
    const int grp = lane >> 2;
    const int cq  = (lane & 3) * 2;
#pragma unroll
    for (int t2 = 0; t2 < 2; ++t2) {
#pragma unroll
        for (int j2 = 0; j2 < 2; ++j2) {
            int r = mw * 32 + t2 * 16 + grp + j2 * 8;
            int m = m0 + r;
            if (r < MOUT && m < MTOT) {
                int h = (m >> 6) & 63, w = m & 63, b = m >> 12;
                if (h < HO && w < WO) {
                    size_t obase = ((size_t)b * COUT) * (HO * WO) + h * WO + w;
#pragma unroll
                    for (int nf = 0; nf < 4; ++nf) {
                        int o = nw * 32 + nf * 8 + cq;
                        out[obase + (size_t)o * (HO * WO)]       = acc[t2][nf][j2 * 2];
                        out[obase + (size_t)(o + 1) * (HO * WO)] = acc[t2][nf][j2 * 2 + 1];
                    }
                }
            }
        }
    }
}

// ---------------- launch ----------------
extern "C" void kernel_launch(void* const* d_in, const int* in_sizes, int n_in,
                              void* d_out, int out_size) {
    const float* x  = (const float*)d_in[0];
    const float* bw = (const float*)d_in[1];
    const float* sw = (const float*)d_in[2];
    const float* ss = (const float*)d_in[3];
    float* out = (float*)d_out;

    static int smem_set = 0;
    if (!smem_set) {
        cudaFuncSetAttribute(gemm_kernel, cudaFuncAttributeMaxDynamicSharedMemorySize, SMEM_TOT);
        smem_set = 1;
    }

    fold_kernel<<<(9 * 64 * KDIM + 255) / 256, 256>>>(bw, sw, ss);
    gemm_kernel<<<NCTA, 256, SMEM_TOT>>>(x, out);
}

// round 12
// speedup vs baseline: 1.2694x; 1.2694x over previous
#include <cuda_runtime.h>
#include <cuda_fp16.h>
#include <cstdint>

// ---------------- problem constants ----------------
#define B_    16
#define CIN   32
#define COUT  64
#define HO    62
#define WO    62
#define HW    4096
#define KDIM  288          // (c,g) = 32*9
#define MTOT  65536        // b*h*w pixels
#define MPAD  65800
#define MOUT  126          // output rows per CTA
#define NCTA  521
#define NSPLIT 3
#define KCPER  6           // 18 k-chunks / 3 splits

// ---------------- device scratch ----------------
__device__ __align__(16) __half g_A[(size_t)MPAD * KDIM];   // fp16 features
__device__ __align__(16) __half g_B[9 * 64 * KDIM];         // [tap][n][k] fp16

// ---------------- helpers ----------------
__device__ __forceinline__ uint32_t smem_u32(const void* p) {
    uint32_t a;
    asm("{ .reg .u64 t; cvta.to.shared.u64 t, %1; cvt.u32.u64 %0, t; }" : "=r"(a) : "l"(p));
    return a;
}
__device__ __forceinline__ void cp16(uint32_t dst, const void* src) {
    asm volatile("cp.async.cg.shared.global [%0], [%1], 16;" :: "r"(dst), "l"(src));
}
#define CP_COMMIT() asm volatile("cp.async.commit_group;" ::: "memory")
#define CP_WAIT1()  asm volatile("cp.async.wait_group 1;" ::: "memory")

#define LDSM4(r, a)                                                          \
    asm volatile("ldmatrix.sync.aligned.m8n8.x4.shared.b16 {%0,%1,%2,%3}, [%4];" \
        : "=r"((r)[0]), "=r"((r)[1]), "=r"((r)[2]), "=r"((r)[3]) : "r"(a))
#define LDSM2(r, a)                                                          \
    asm volatile("ldmatrix.sync.aligned.m8n8.x2.shared.b16 {%0,%1}, [%2];"   \
        : "=r"((r)[0]), "=r"((r)[1]) : "r"(a))
#define MMA(d, a, b)                                                         \
    asm volatile("mma.sync.aligned.m16n8k16.row.col.f32.f16.f16.f32 "        \
        "{%0,%1,%2,%3}, {%4,%5,%6,%7}, {%8,%9}, {%0,%1,%2,%3};"              \
        : "+f"((d)[0]), "+f"((d)[1]), "+f"((d)[2]), "+f"((d)[3])             \
        : "r"((a)[0]), "r"((a)[1]), "r"((a)[2]), "r"((a)[3]),                \
          "r"((b)[0]), "r"((b)[1]))

// ---------------- kernel 0: zero the (poisoned) output ----------------
__global__ void zero_kernel(float4* __restrict__ out, int n4) {
    int i = blockIdx.x * blockDim.x + threadIdx.x;
    if (i < n4) out[i] = make_float4(0.f, 0.f, 0.f, 0.f);
}

// ---------------- kernel 1: features -> fp16 A (direct B-spline eval) -----
#define SROW 290
__global__ void __launch_bounds__(256) feat_kernel(const float* __restrict__ x) {
    __shared__ __half SA[32][SROW];
    const int m0  = blockIdx.x * 32;
    const int b   = m0 >> 12;
    const int hw0 = m0 & 4095;
    const int t   = threadIdx.x;
    const int i   = t & 31;
    const int c0  = t >> 5;

#pragma unroll
    for (int cc = 0; cc < 4; ++cc) {
        int c = c0 + cc * 8;
        float v = x[((size_t)(b * CIN + c) << 12) + hw0 + i];
        __half* row = &SA[i][c * 9];
        row[0] = __float2half(__fdividef(v, 1.0f + __expf(-v)));
#pragma unroll
        for (int g = 1; g < 9; ++g) row[g] = __ushort_as_half((unsigned short)0);
        float s = (v + 2.2f) * 2.5f;
        float fs = floorf(s);
        int idx = (int)fs;
        if (idx >= 0 && idx <= 10) {
            float u  = s - fs;
            float um = 1.0f - u;
            float u2 = u * u, u3 = u2 * u;
            const float k6 = 1.0f / 6.0f;
            float w0 = um * um * um * k6;
            float w1 = (3.0f * u3 - 6.0f * u2 + 4.0f) * k6;
            float w2 = (-3.0f * u3 + 3.0f * u2 + 3.0f * u + 1.0f) * k6;
            float w3 = u3 * k6;
            int j = idx - 3;
            if (j     >= 0 && j     <= 7) row[1 + j] = __float2half(w0);
            if (j + 1 >= 0 && j + 1 <= 7) row[2 + j] = __float2half(w1);
            if (j + 2 >= 0 && j + 2 <= 7) row[3 + j] = __float2half(w2);
            if (j + 3 >= 0 && j + 3 <= 7) row[4 + j] = __float2half(w3);
        }
    }
    __syncthreads();

#pragma unroll
    for (int u = t; u < 1152; u += 256) {
        int row = u / 36;
        int col = (u - row * 36) * 8;
        const uint32_t* pa = (const uint32_t*)&SA[row][col];
        uint4 va; va.x = pa[0]; va.y = pa[1]; va.z = pa[2]; va.w = pa[3];
        *(uint4*)&g_A[(size_t)(m0 + row) * KDIM + col] = va;
    }
}

// ---------------- kernel 2: fold weights -> fp16 ----------------
__global__ void fold_kernel(const float* __restrict__ bw,
                            const float* __restrict__ sw,
                            const float* __restrict__ ss) {
    int i = blockIdx.x * blockDim.x + threadIdx.x;    // [tap][n][k]
    if (i >= 9 * 64 * KDIM) return;
    int k = i % KDIM;
    int n = (i / KDIM) & 63;
    int p = i / (KDIM * 64);
    int c = k / 9, g = k % 9;
    int ocp = (n * CIN + c) * 9 + p;
    float val = (g == 0) ? bw[ocp] : sw[ocp * 8 + (g - 1)] * ss[ocp];
    g_B[i] = __float2half(val);
}

// ---------------- kernel 3: mma.sync fp16 GEMM, split-K 3, occ 2 ----------
#define APITCH 48
#define AROWS  260
#define BOFF   (AROWS * APITCH)          // 12480
#define BTILE  (64 * APITCH)             // 3072
#define BUFSZ  (BOFF + 9 * BTILE)        // 40128
#define SMEM_TOT (2 * BUFSZ)             // 80256

__global__ void __launch_bounds__(256, 2) gemm_kernel(float* __restrict__ out) {
    extern __shared__ __align__(16) char smem[];
    uint32_t sb = smem_u32(smem);
    const int tid  = threadIdx.x;
    const int lane = tid & 31;
    const int wid  = tid >> 5;
    const int mw = wid & 3;
    const int nw = wid >> 2;
    const int m0 = blockIdx.x * MOUT;
    const int k0 = blockIdx.y * KCPER;   // this split's first k-chunk

    const char* Ap = (const char*)g_A;
    const char* Bp = (const char*)g_B;

    auto prefetch = [&](int kc, uint32_t bb) {
#pragma unroll
        for (int i = 0; i < 7; ++i) {
            int u = tid + i * 256;
            if (u >= 1668) break;
            const char* src;
            uint32_t dst;
            if (u < 516) {
                int row = u >> 1, half = u & 1;
                src = Ap + (size_t)(m0 + row) * (KDIM * 2) + kc * 32 + half * 16;
                dst = bb + row * APITCH + half * 16;
            } else {
                int v = u - 516;
                int tile = v >> 7, row = (v >> 1) & 63, half = v & 1;
                src = Bp + (size_t)(tile * 64 + row) * (KDIM * 2) + kc * 32 + half * 16;
                dst = bb + BOFF + tile * BTILE + row * APITCH + half * 16;
            }
            cp16(dst, src);
        }
    };

    float acc[2][4][4];
#pragma unroll
    for (int b = 0; b < 2; ++b)
#pragma unroll
        for (int c = 0; c < 4; ++c)
#pragma unroll
            for (int d = 0; d < 4; ++d) acc[b][c][d] = 0.0f;

    const uint32_t a_lane = (uint32_t)((lane & 15) * APITCH + (lane >> 4) * 16);
    const uint32_t b_lane = (uint32_t)((lane & 7) * APITCH + ((lane >> 3) & 1) * 16);

    prefetch(k0, sb);
    CP_COMMIT();

    for (int kk = 0; kk < KCPER; ++kk) {
        if (kk < KCPER - 1) prefetch(k0 + kk + 1, sb + ((kk + 1) & 1) * BUFSZ);
        CP_COMMIT();
        CP_WAIT1();
        __syncthreads();

        const uint32_t bb = sb + (kk & 1) * BUFSZ;
#pragma unroll
        for (int kh = 0; kh < 3; ++kh)
#pragma unroll
            for (int kw = 0; kw < 3; ++kw) {
                uint32_t ah[2][4];
#pragma unroll
                for (int t2 = 0; t2 < 2; ++t2) {
                    uint32_t ra = bb + (kh * 64 + kw + mw * 32 + t2 * 16) * APITCH + a_lane;
                    LDSM4(ah[t2], ra);
                }
                const int tile = kh * 3 + kw;
#pragma unroll
                for (int nf = 0; nf < 4; ++nf) {
                    uint32_t rb = bb + BOFF + tile * BTILE
                                + (nw * 32 + nf * 8) * APITCH + b_lane;
                    uint32_t bfr[2];
                    LDSM2(bfr, rb);
#pragma unroll
                    for (int t2 = 0; t2 < 2; ++t2)
                        MMA(acc[t2][nf], ah[t2], bfr);
                }
            }
        __syncthreads();
    }

    // ---- epilogue: atomic accumulate into gmem ----
    const int grp = lane >> 2;
    const int cq  = (lane & 3) * 2;
#pragma unroll
    for (int t2 = 0; t2 < 2; ++t2) {
#pragma unroll
        for (int j2 = 0; j2 < 2; ++j2) {
            int r = mw * 32 + t2 * 16 + grp + j2 * 8;
            int m = m0 + r;
            if (r < MOUT && m < MTOT) {
                int h = (m >> 6) & 63, w = m & 63, b = m >> 12;
                if (h < HO && w < WO) {
                    size_t obase = ((size_t)b * COUT) * (HO * WO) + h * WO + w;
#pragma unroll
                    for (int nf = 0; nf < 4; ++nf) {
                        int o = nw * 32 + nf * 8 + cq;
                        atomicAdd(&out[obase + (size_t)o * (HO * WO)],       acc[t2][nf][j2 * 2]);
                        atomicAdd(&out[obase + (size_t)(o + 1) * (HO * WO)], acc[t2][nf][j2 * 2 + 1]);
                    }
                }
            }
        }
    }
}

// ---------------- launch ----------------
extern "C" void kernel_launch(void* const* d_in, const int* in_sizes, int n_in,
                              void* d_out, int out_size) {
    const float* x  = (const float*)d_in[0];
    const float* bw = (const float*)d_in[1];
    const float* sw = (const float*)d_in[2];
    const float* ss = (const float*)d_in[3];
    float* out = (float*)d_out;

    static int smem_set = 0;
    if (!smem_set) {
        cudaFuncSetAttribute(gemm_kernel, cudaFuncAttributeMaxDynamicSharedMemorySize, SMEM_TOT);
        smem_set = 1;
    }

    int n4 = out_size / 4;   // out_size = 16*64*62*62 = 3936256, divisible by 4
    zero_kernel<<<(n4 + 255) / 256, 256>>>((float4*)out, n4);
    feat_kernel<<<MTOT / 32, 256>>>(x);
    fold_kernel<<<(9 * 64 * KDIM + 255) / 256, 256>>>(bw, sw, ss);
    gemm_kernel<<<dim3(NCTA, NSPLIT), 256, SMEM_TOT>>>(out);
}

// round 13
// speedup vs baseline: 1.2985x; 1.0229x over previous
#include <cuda_runtime.h>
#include <cuda_fp16.h>
#include <cstdint>

// ---------------- problem constants ----------------
#define B_    16
#define CIN   32
#define COUT  64
#define HO    62
#define WO    62
#define HW    4096
#define KDIM  288          // (c,g) = 32*9
#define MTOT  65536        // b*h*w pixels
#define MPAD  65800
#define MOUT  126          // output rows per CTA
#define NCTA  521
#define NSPLIT 3
#define KCPER  6           // 18 k-chunks / 3 splits

// ---------------- device scratch ----------------
__device__ __align__(16) __half g_A[(size_t)MPAD * KDIM];   // fp16 features
__device__ __align__(16) __half g_B[9 * 64 * KDIM];         // [tap][n][k] fp16

// ---------------- helpers ----------------
__device__ __forceinline__ uint32_t smem_u32(const void* p) {
    uint32_t a;
    asm("{ .reg .u64 t; cvta.to.shared.u64 t, %1; cvt.u32.u64 %0, t; }" : "=r"(a) : "l"(p));
    return a;
}
__device__ __forceinline__ void cp16(uint32_t dst, const void* src) {
    asm volatile("cp.async.cg.shared.global [%0], [%1], 16;" :: "r"(dst), "l"(src));
}
#define CP_COMMIT() asm volatile("cp.async.commit_group;" ::: "memory")
#define CP_WAIT1()  asm volatile("cp.async.wait_group 1;" ::: "memory")

#define LDSM4(r, a)                                                          \
    asm volatile("ldmatrix.sync.aligned.m8n8.x4.shared.b16 {%0,%1,%2,%3}, [%4];" \
        : "=r"((r)[0]), "=r"((r)[1]), "=r"((r)[2]), "=r"((r)[3]) : "r"(a))
#define MMA(d, a, b0, b1)                                                    \
    asm volatile("mma.sync.aligned.m16n8k16.row.col.f32.f16.f16.f32 "        \
        "{%0,%1,%2,%3}, {%4,%5,%6,%7}, {%8,%9}, {%0,%1,%2,%3};"              \
        : "+f"((d)[0]), "+f"((d)[1]), "+f"((d)[2]), "+f"((d)[3])             \
        : "r"((a)[0]), "r"((a)[1]), "r"((a)[2]), "r"((a)[3]),                \
          "r"(b0), "r"(b1))

// ---------------- kernel 0: zero the (poisoned) output ----------------
__global__ void zero_kernel(float4* __restrict__ out, int n4) {
    int i = blockIdx.x * blockDim.x + threadIdx.x;
    if (i < n4) out[i] = make_float4(0.f, 0.f, 0.f, 0.f);
}

// ---------------- kernel 1: features -> fp16 A (direct B-spline eval) -----
#define SROW 290
__global__ void __launch_bounds__(256) feat_kernel(const float* __restrict__ x) {
    __shared__ __half SA[32][SROW];
    const int m0  = blockIdx.x * 32;
    const int b   = m0 >> 12;
    const int hw0 = m0 & 4095;
    const int t   = threadIdx.x;
    const int i   = t & 31;
    const int c0  = t >> 5;

#pragma unroll
    for (int cc = 0; cc < 4; ++cc) {
        int c = c0 + cc * 8;
        float v = x[((size_t)(b * CIN + c) << 12) + hw0 + i];
        __half* row = &SA[i][c * 9];
        row[0] = __float2half(__fdividef(v, 1.0f + __expf(-v)));
#pragma unroll
        for (int g = 1; g < 9; ++g) row[g] = __ushort_as_half((unsigned short)0);
        float s = (v + 2.2f) * 2.5f;
        float fs = floorf(s);
        int idx = (int)fs;
        if (idx >= 0 && idx <= 10) {
            float u  = s - fs;
            float um = 1.0f - u;
            float u2 = u * u, u3 = u2 * u;
            const float k6 = 1.0f / 6.0f;
            float w0 = um * um * um * k6;
            float w1 = (3.0f * u3 - 6.0f * u2 + 4.0f) * k6;
            float w2 = (-3.0f * u3 + 3.0f * u2 + 3.0f * u + 1.0f) * k6;
            float w3 = u3 * k6;
            int j = idx - 3;
            if (j     >= 0 && j     <= 7) row[1 + j] = __float2half(w0);
            if (j + 1 >= 0 && j + 1 <= 7) row[2 + j] = __float2half(w1);
            if (j + 2 >= 0 && j + 2 <= 7) row[3 + j] = __float2half(w2);
            if (j + 3 >= 0 && j + 3 <= 7) row[4 + j] = __float2half(w3);
        }
    }
    __syncthreads();

#pragma unroll
    for (int u = t; u < 1152; u += 256) {
        int row = u / 36;
        int col = (u - row * 36) * 8;
        const uint32_t* pa = (const uint32_t*)&SA[row][col];
        uint4 va; va.x = pa[0]; va.y = pa[1]; va.z = pa[2]; va.w = pa[3];
        *(uint4*)&g_A[(size_t)(m0 + row) * KDIM + col] = va;
    }
}

// ---------------- kernel 2: fold weights -> fp16 ----------------
__global__ void fold_kernel(const float* __restrict__ bw,
                            const float* __restrict__ sw,
                            const float* __restrict__ ss) {
    int i = blockIdx.x * blockDim.x + threadIdx.x;    // [tap][n][k]
    if (i >= 9 * 64 * KDIM) return;
    int k = i % KDIM;
    int n = (i / KDIM) & 63;
    int p = i / (KDIM * 64);
    int c = k / 9, g = k % 9;
    int ocp = (n * CIN + c) * 9 + p;
    float val = (g == 0) ? bw[ocp] : sw[ocp * 8 + (g - 1)] * ss[ocp];
    g_B[i] = __float2half(val);
}

// ---------------- kernel 3: mma.sync fp16 GEMM, split-K 3, occ 2 ----------
#define APITCH 48
#define AROWS  260
#define BOFF   (AROWS * APITCH)          // 12480
#define BTILE  (64 * APITCH)             // 3072
#define BUFSZ  (BOFF + 9 * BTILE)        // 40128
#define SMEM_TOT (2 * BUFSZ)             // 80256

__global__ void __launch_bounds__(256, 2) gemm_kernel(float* __restrict__ out) {
    extern __shared__ __align__(16) char smem[];
    uint32_t sb = smem_u32(smem);
    const int tid  = threadIdx.x;
    const int lane = tid & 31;
    const int wid  = tid >> 5;
    const int mw = wid & 3;
    const int nw = wid >> 2;
    const int m0 = blockIdx.x * MOUT;
    const int k0 = blockIdx.y * KCPER;

    const char* Ap = (const char*)g_A;
    const char* Bp = (const char*)g_B;

    auto prefetch = [&](int kc, uint32_t bb) {
#pragma unroll
        for (int i = 0; i < 7; ++i) {
            int u = tid + i * 256;
            if (u >= 1668) break;
            const char* src;
            uint32_t dst;
            if (u < 516) {
                int row = u >> 1, half = u & 1;
                src = Ap + (size_t)(m0 + row) * (KDIM * 2) + kc * 32 + half * 16;
                dst = bb + row * APITCH + half * 16;
            } else {
                int v = u - 516;
                int tile = v >> 7, row = (v >> 1) & 63, half = v & 1;
                src = Bp + (size_t)(tile * 64 + row) * (KDIM * 2) + kc * 32 + half * 16;
                dst = bb + BOFF + tile * BTILE + row * APITCH + half * 16;
            }
            cp16(dst, src);
        }
    };

    float acc[2][4][4];
#pragma unroll
    for (int b = 0; b < 2; ++b)
#pragma unroll
        for (int c = 0; c < 4; ++c)
#pragma unroll
            for (int d = 0; d < 4; ++d) acc[b][c][d] = 0.0f;

    const uint32_t a_lane = (uint32_t)((lane & 15) * APITCH + (lane >> 4) * 16);
    // B x4 lane map: lanes 0-15 -> first n8 fragment rows (k-halves), 16-31 -> next n8
    const uint32_t b4_lane = (uint32_t)((((lane & 7) + ((lane >> 4) << 3)) * APITCH)
                                        + (((lane >> 3) & 1) * 16));

    prefetch(k0, sb);
    CP_COMMIT();

    for (int kk = 0; kk < KCPER; ++kk) {
        if (kk < KCPER - 1) prefetch(k0 + kk + 1, sb + ((kk + 1) & 1) * BUFSZ);
        CP_COMMIT();
        CP_WAIT1();
        __syncthreads();

        const uint32_t bb = sb + (kk & 1) * BUFSZ;
#pragma unroll
        for (int tap = 0; tap < 9; ++tap) {
            const int kh = tap / 3, kw = tap - 3 * (tap / 3);
            // batched fragment loads: 2xA LDSM4 + 2xB LDSM4 (4-deep MLP)
            uint32_t ah[2][4], bf[2][4];
#pragma unroll
            for (int t2 = 0; t2 < 2; ++t2) {
                uint32_t ra = bb + (kh * 64 + kw + mw * 32 + t2 * 16) * APITCH + a_lane;
                LDSM4(ah[t2], ra);
            }
#pragma unroll
            for (int nf2 = 0; nf2 < 2; ++nf2) {
                uint32_t rb = bb + BOFF + tap * BTILE
                            + (nw * 32 + nf2 * 16) * APITCH + b4_lane;
                LDSM4(bf[nf2], rb);
            }
            // 16 MMAs, 8 independent accumulator chains
#pragma unroll
            for (int nf2 = 0; nf2 < 2; ++nf2)
#pragma unroll
                for (int hf = 0; hf < 2; ++hf)
#pragma unroll
                    for (int t2 = 0; t2 < 2; ++t2)
                        MMA(acc[t2][nf2 * 2 + hf], ah[t2],
                            bf[nf2][hf * 2], bf[nf2][hf * 2 + 1]);
        }
        __syncthreads();
    }

    // ---- epilogue: atomic accumulate into gmem ----
    const int grp = lane >> 2;
    const int cq  = (lane & 3) * 2;
#pragma unroll
    for (int t2 = 0; t2 < 2; ++t2) {
#pragma unroll
        for (int j2 = 0; j2 < 2; ++j2) {
            int r = mw * 32 + t2 * 16 + grp + j2 * 8;
            int m = m0 + r;
            if (r < MOUT && m < MTOT) {
                int h = (m >> 6) & 63, w = m & 63, b = m >> 12;
                if (h < HO && w < WO) {
                    size_t obase = ((size_t)b * COUT) * (HO * WO) + h * WO + w;
#pragma unroll
                    for (int nf = 0; nf < 4; ++nf) {
                        int o = nw * 32 + nf * 8 + cq;
                        atomicAdd(&out[obase + (size_t)o * (HO * WO)],       acc[t2][nf][j2 * 2]);
                        atomicAdd(&out[obase + (size_t)(o + 1) * (HO * WO)], acc[t2][nf][j2 * 2 + 1]);
                    }
                }
            }
        }
    }
}

// ---------------- launch ----------------
extern "C" void kernel_launch(void* const* d_in, const int* in_sizes, int n_in,
                              void* d_out, int out_size) {
    const float* x  = (const float*)d_in[0];
    const float* bw = (const float*)d_in[1];
    const float* sw = (const float*)d_in[2];
    const float* ss = (const float*)d_in[3];
    float* out = (float*)d_out;

    static int smem_set = 0;
    if (!smem_set) {
        cudaFuncSetAttribute(gemm_kernel, cudaFuncAttributeMaxDynamicSharedMemorySize, SMEM_TOT);
        smem_set = 1;
    }

    int n4 = out_size / 4;
    zero_kernel<<<(n4 + 255) / 256, 256>>>((float4*)out, n4);
    feat_kernel<<<MTOT / 32, 256>>>(x);
    fold_kernel<<<(9 * 64 * KDIM + 255) / 256, 256>>>(bw, sw, ss);
    gemm_kernel<<<dim3(NCTA, NSPLIT), 256, SMEM_TOT>>>(out);
}

// round 14
// speedup vs baseline: 1.5250x; 1.1744x over previous
#include <cuda_runtime.h>
#include <cuda_fp16.h>
#include <cstdint>

// ---------------- problem constants ----------------
#define B_    16
#define CIN   32
#define COUT  64
#define HO    62
#define WO    62
#define HW    4096
#define KDIM  288          // (c,g) = 32*9
#define MTOT  65536        // b*h*w pixels
#define MPAD  65800
#define MOUT  126          // output rows per CTA
#define NCTA  521
#define NSPLIT 3
#define KCPER  6           // 18 k-chunks / 3 splits

// ---------------- device scratch ----------------
__device__ __align__(16) __half g_A[(size_t)MPAD * KDIM];   // fp16 features
__device__ __align__(16) __half g_B[9 * 64 * KDIM];         // [tap][n][k] fp16

// ---------------- helpers ----------------
__device__ __forceinline__ uint32_t smem_u32(const void* p) {
    uint32_t a;
    asm("{ .reg .u64 t; cvta.to.shared.u64 t, %1; cvt.u32.u64 %0, t; }" : "=r"(a) : "l"(p));
    return a;
}
__device__ __forceinline__ void cp16(uint32_t dst, const void* src) {
    asm volatile("cp.async.cg.shared.global [%0], [%1], 16;" :: "r"(dst), "l"(src));
}
#define CP_COMMIT() asm volatile("cp.async.commit_group;" ::: "memory")
#define CP_WAIT1()  asm volatile("cp.async.wait_group 1;" ::: "memory")

#define LDSM4(r, a)                                                          \
    asm volatile("ldmatrix.sync.aligned.m8n8.x4.shared.b16 {%0,%1,%2,%3}, [%4];" \
        : "=r"((r)[0]), "=r"((r)[1]), "=r"((r)[2]), "=r"((r)[3]) : "r"(a))
#define MMA(d, a, b0, b1)                                                    \
    asm volatile("mma.sync.aligned.m16n8k16.row.col.f32.f16.f16.f32 "        \
        "{%0,%1,%2,%3}, {%4,%5,%6,%7}, {%8,%9}, {%0,%1,%2,%3};"              \
        : "+f"((d)[0]), "+f"((d)[1]), "+f"((d)[2]), "+f"((d)[3])             \
        : "r"((a)[0]), "r"((a)[1]), "r"((a)[2]), "r"((a)[3]),                \
          "r"(b0), "r"(b1))

// ---------------- kernel 0: zero the (poisoned) output ----------------
__global__ void zero_kernel(float4* __restrict__ out, int n4) {
    int i = blockIdx.x * blockDim.x + threadIdx.x;
    if (i < n4) out[i] = make_float4(0.f, 0.f, 0.f, 0.f);
}

// ---------------- kernel 1: features -> fp16 A (direct B-spline eval) -----
#define SROW 290
__global__ void __launch_bounds__(256) feat_kernel(const float* __restrict__ x) {
    __shared__ __half SA[32][SROW];
    const int m0  = blockIdx.x * 32;
    const int b   = m0 >> 12;
    const int hw0 = m0 & 4095;
    const int t   = threadIdx.x;
    const int i   = t & 31;
    const int c0  = t >> 5;

#pragma unroll
    for (int cc = 0; cc < 4; ++cc) {
        int c = c0 + cc * 8;
        float v = x[((size_t)(b * CIN + c) << 12) + hw0 + i];
        __half* row = &SA[i][c * 9];
        row[0] = __float2half(__fdividef(v, 1.0f + __expf(-v)));
#pragma unroll
        for (int g = 1; g < 9; ++g) row[g] = __ushort_as_half((unsigned short)0);
        float s = (v + 2.2f) * 2.5f;
        float fs = floorf(s);
        int idx = (int)fs;
        if (idx >= 0 && idx <= 10) {
            float u  = s - fs;
            float um = 1.0f - u;
            float u2 = u * u, u3 = u2 * u;
            const float k6 = 1.0f / 6.0f;
            float w0 = um * um * um * k6;
            float w1 = (3.0f * u3 - 6.0f * u2 + 4.0f) * k6;
            float w2 = (-3.0f * u3 + 3.0f * u2 + 3.0f * u + 1.0f) * k6;
            float w3 = u3 * k6;
            int j = idx - 3;
            if (j     >= 0 && j     <= 7) row[1 + j] = __float2half(w0);
            if (j + 1 >= 0 && j + 1 <= 7) row[2 + j] = __float2half(w1);
            if (j + 2 >= 0 && j + 2 <= 7) row[3 + j] = __float2half(w2);
            if (j + 3 >= 0 && j + 3 <= 7) row[4 + j] = __float2half(w3);
        }
    }
    __syncthreads();

#pragma unroll
    for (int u = t; u < 1152; u += 256) {
        int row = u / 36;
        int col = (u - row * 36) * 8;
        const uint32_t* pa = (const uint32_t*)&SA[row][col];
        uint4 va; va.x = pa[0]; va.y = pa[1]; va.z = pa[2]; va.w = pa[3];
        *(uint4*)&g_A[(size_t)(m0 + row) * KDIM + col] = va;
    }
}

// ---------------- kernel 2: fold weights -> fp16 ----------------
__global__ void fold_kernel(const float* __restrict__ bw,
                            const float* __restrict__ sw,
                            const float* __restrict__ ss) {
    int i = blockIdx.x * blockDim.x + threadIdx.x;    // [tap][n][k]
    if (i >= 9 * 64 * KDIM) return;
    int k = i % KDIM;
    int n = (i / KDIM) & 63;
    int p = i / (KDIM * 64);
    int c = k / 9, g = k % 9;
    int ocp = (n * CIN + c) * 9 + p;
    float val = (g == 0) ? bw[ocp] : sw[ocp * 8 + (g - 1)] * ss[ocp];
    g_B[i] = __float2half(val);
}

// ---------------- kernel 3: fp16 GEMM, pitch-32 swizzle, occ 3 ------------
// chunk(row, khalf) at row*32 + ((khalf ^ ((row>>2)&1))<<4) -> conflict-free
// LDSM over any 8 consecutive rows; cp.async writes use the same mapping.
#define AROWS  258
#define BOFF   (AROWS * 32)              // 8256
#define BTILE  (64 * 32)                 // 2048
#define BUFSZ  (BOFF + 9 * BTILE)        // 26688
#define SMEM_TOT (2 * BUFSZ)             // 53376 -> 3 CTAs/SM

__global__ void __launch_bounds__(256, 3) gemm_kernel(float* __restrict__ out) {
    extern __shared__ __align__(16) char smem[];
    uint32_t sb = smem_u32(smem);
    const int tid  = threadIdx.x;
    const int lane = tid & 31;
    const int wid  = tid >> 5;
    const int mw = wid & 3;
    const int nw = wid >> 2;
    const int m0 = blockIdx.x * MOUT;
    const int k0 = blockIdx.y * KCPER;

    const char* Ap = (const char*)g_A;
    const char* Bp = (const char*)g_B;

    auto prefetch = [&](int kc, uint32_t bb) {
#pragma unroll
        for (int i = 0; i < 7; ++i) {
            int u = tid + i * 256;
            if (u >= 1668) break;
            const char* src;
            uint32_t dst;
            if (u < 516) {
                int row = u >> 1, half = u & 1;
                src = Ap + (size_t)(m0 + row) * (KDIM * 2) + kc * 32 + half * 16;
                dst = bb + row * 32 + ((half ^ ((row >> 2) & 1)) << 4);
            } else {
                int v = u - 516;
                int tile = v >> 7, row = (v >> 1) & 63, half = v & 1;
                src = Bp + (size_t)(tile * 64 + row) * (KDIM * 2) + kc * 32 + half * 16;
                dst = bb + BOFF + tile * BTILE + row * 32
                    + ((half ^ ((row >> 2) & 1)) << 4);
            }
            cp16(dst, src);
        }
    };

    float acc[2][4][4];
#pragma unroll
    for (int b = 0; b < 2; ++b)
#pragma unroll
        for (int c = 0; c < 4; ++c)
#pragma unroll
            for (int d = 0; d < 4; ++d) acc[b][c][d] = 0.0f;

    // --- per-thread swizzled lane offsets (zero inner-loop ALU) ---
    const int ll  = lane & 15;           // A fragment row-within-16
    const int kh4 = lane >> 4;           // A k-half
    uint32_t aoff[3];
#pragma unroll
    for (int kw = 0; kw < 3; ++kw)
        aoff[kw] = (uint32_t)(ll * 32 + (((((kw + ll) >> 2) & 1) ^ kh4) << 4));
    const int lb  = (lane & 7) + ((lane >> 4) << 3);   // B row-within-16
    const int khb = (lane >> 3) & 1;                   // B k-half
    const uint32_t boff = (uint32_t)(lb * 32 + ((((lb >> 2) & 1) ^ khb) << 4));

    prefetch(k0, sb);
    CP_COMMIT();

    for (int kk = 0; kk < KCPER; ++kk) {
        if (kk < KCPER - 1) prefetch(k0 + kk + 1, sb + ((kk + 1) & 1) * BUFSZ);
        CP_COMMIT();
        CP_WAIT1();
        __syncthreads();

        const uint32_t bb = sb + (kk & 1) * BUFSZ;
#pragma unroll
        for (int tap = 0; tap < 9; ++tap) {
            const int kh = tap / 3, kw = tap - 3 * (tap / 3);
            uint32_t ah[2][4], bf[2][4];
#pragma unroll
            for (int t2 = 0; t2 < 2; ++t2) {
                uint32_t ra = bb + (uint32_t)((kh * 64 + kw + mw * 32 + t2 * 16) * 32)
                            + aoff[kw];
                LDSM4(ah[t2], ra);
            }
#pragma unroll
            for (int nf2 = 0; nf2 < 2; ++nf2) {
                uint32_t rb = bb + BOFF + (uint32_t)(tap * BTILE)
                            + (uint32_t)((nw * 32 + nf2 * 16) * 32) + boff;
                LDSM4(bf[nf2], rb);
            }
#pragma unroll
            for (int nf2 = 0; nf2 < 2; ++nf2)
#pragma unroll
                for (int hf = 0; hf < 2; ++hf)
#pragma unroll
                    for (int t2 = 0; t2 < 2; ++t2)
                        MMA(acc[t2][nf2 * 2 + hf], ah[t2],
                            bf[nf2][hf * 2], bf[nf2][hf * 2 + 1]);
        }
        __syncthreads();
    }

    // ---- epilogue: atomic accumulate into gmem ----
    const int grp = lane >> 2;
    const int cq  = (lane & 3) * 2;
#pragma unroll
    for (int t2 = 0; t2 < 2; ++t2) {
#pragma unroll
        for (int j2 = 0; j2 < 2; ++j2) {
            int r = mw * 32 + t2 * 16 + grp + j2 * 8;
            int m = m0 + r;
            if (r < MOUT && m < MTOT) {
                int h = (m >> 6) & 63, w = m & 63, b = m >> 12;
                if (h < HO && w < WO) {
                    size_t obase = ((size_t)b * COUT) * (HO * WO) + h * WO + w;
#pragma unroll
                    for (int nf = 0; nf < 4; ++nf) {
                        int o = nw * 32 + nf * 8 + cq;
                        atomicAdd(&out[obase + (size_t)o * (HO * WO)],       acc[t2][nf][j2 * 2]);
                        atomicAdd(&out[obase + (size_t)(o + 1) * (HO * WO)], acc[t2][nf][j2 * 2 + 1]);
                    }
                }
            }
        }
    }
}

// ---------------- launch ----------------
extern "C" void kernel_launch(void* const* d_in, const int* in_sizes, int n_in,
                              void* d_out, int out_size) {
    const float* x  = (const float*)d_in[0];
    const float* bw = (const float*)d_in[1];
    const float* sw = (const float*)d_in[2];
    const float* ss = (const float*)d_in[3];
    float* out = (float*)d_out;

    static int smem_set = 0;
    if (!smem_set) {
        cudaFuncSetAttribute(gemm_kernel, cudaFuncAttributeMaxDynamicSharedMemorySize, SMEM_TOT);
        smem_set = 1;
    }

    int n4 = out_size / 4;
    zero_kernel<<<(n4 + 255) / 256, 256>>>((float4*)out, n4);
    feat_kernel<<<MTOT / 32, 256>>>(x);
    fold_kernel<<<(9 * 64 * KDIM + 255) / 256, 256>>>(bw, sw, ss);
    gemm_kernel<<<dim3(NCTA, NSPLIT), 256, SMEM_TOT>>>(out);
}

// round 15
// speedup vs baseline: 1.5590x; 1.0222x over previous
#include <cuda_runtime.h>
#include <cuda_fp16.h>
#include <cstdint>

// ---------------- problem constants ----------------
#define B_    16
#define CIN   32
#define COUT  64
#define HO    62
#define WO    62
#define HW    4096
#define KDIM  288          // (c,g) = 32*9
#define MTOT  65536        // b*h*w pixels
#define MPAD  65800
#define MOUT  126          // output rows per CTA
#define NCTA  521
#define NSPLIT 3
#define KCPER  6           // 18 k-chunks / 3 splits

// ---------------- device scratch ----------------
__device__ __align__(16) __half g_A[(size_t)MPAD * KDIM];   // fp16 features
__device__ __align__(16) __half g_B[9 * 64 * KDIM];         // [tap][n][k] fp16

// ---------------- helpers ----------------
__device__ __forceinline__ uint32_t smem_u32(const void* p) {
    uint32_t a;
    asm("{ .reg .u64 t; cvta.to.shared.u64 t, %1; cvt.u32.u64 %0, t; }" : "=r"(a) : "l"(p));
    return a;
}
__device__ __forceinline__ void cp16(uint32_t dst, const void* src) {
    asm volatile("cp.async.cg.shared.global [%0], [%1], 16;" :: "r"(dst), "l"(src));
}
#define CP_COMMIT() asm volatile("cp.async.commit_group;" ::: "memory")
#define CP_WAIT1()  asm volatile("cp.async.wait_group 1;" ::: "memory")

#define LDSM4(r, a)                                                          \
    asm volatile("ldmatrix.sync.aligned.m8n8.x4.shared.b16 {%0,%1,%2,%3}, [%4];" \
        : "=r"((r)[0]), "=r"((r)[1]), "=r"((r)[2]), "=r"((r)[3]) : "r"(a))
#define MMA(d, a, b0, b1)                                                    \
    asm volatile("mma.sync.aligned.m16n8k16.row.col.f32.f16.f16.f32 "        \
        "{%0,%1,%2,%3}, {%4,%5,%6,%7}, {%8,%9}, {%0,%1,%2,%3};"              \
        : "+f"((d)[0]), "+f"((d)[1]), "+f"((d)[2]), "+f"((d)[3])             \
        : "r"((a)[0]), "r"((a)[1]), "r"((a)[2]), "r"((a)[3]),                \
          "r"(b0), "r"(b1))

// ---------------- kernel 0: zero the (poisoned) output ----------------
__global__ void zero_kernel(float4* __restrict__ out, int n4) {
    int i = blockIdx.x * blockDim.x + threadIdx.x;
    if (i < n4) out[i] = make_float4(0.f, 0.f, 0.f, 0.f);
}

// ---------------- kernel 1: features -> fp16 A (direct B-spline eval) -----
#define SROW 290
__global__ void __launch_bounds__(256) feat_kernel(const float* __restrict__ x) {
    __shared__ __half SA[32][SROW];
    const int m0  = blockIdx.x * 32;
    const int b   = m0 >> 12;
    const int hw0 = m0 & 4095;
    const int t   = threadIdx.x;
    const int i   = t & 31;
    const int c0  = t >> 5;

#pragma unroll
    for (int cc = 0; cc < 4; ++cc) {
        int c = c0 + cc * 8;
        float v = x[((size_t)(b * CIN + c) << 12) + hw0 + i];
        __half* row = &SA[i][c * 9];
        row[0] = __float2half(__fdividef(v, 1.0f + __expf(-v)));
#pragma unroll
        for (int g = 1; g < 9; ++g) row[g] = __ushort_as_half((unsigned short)0);
        float s = (v + 2.2f) * 2.5f;
        float fs = floorf(s);
        int idx = (int)fs;
        if (idx >= 0 && idx <= 10) {
            float u  = s - fs;
            float um = 1.0f - u;
            float u2 = u * u, u3 = u2 * u;
            const float k6 = 1.0f / 6.0f;
            float w0 = um * um * um * k6;
            float w1 = (3.0f * u3 - 6.0f * u2 + 4.0f) * k6;
            float w2 = (-3.0f * u3 + 3.0f * u2 + 3.0f * u + 1.0f) * k6;
            float w3 = u3 * k6;
            int j = idx - 3;
            if (j     >= 0 && j     <= 7) row[1 + j] = __float2half(w0);
            if (j + 1 >= 0 && j + 1 <= 7) row[2 + j] = __float2half(w1);
            if (j + 2 >= 0 && j + 2 <= 7) row[3 + j] = __float2half(w2);
            if (j + 3 >= 0 && j + 3 <= 7) row[4 + j] = __float2half(w3);
        }
    }
    __syncthreads();

#pragma unroll
    for (int u = t; u < 1152; u += 256) {
        int row = u / 36;
        int col = (u - row * 36) * 8;
        const uint32_t* pa = (const uint32_t*)&SA[row][col];
        uint4 va; va.x = pa[0]; va.y = pa[1]; va.z = pa[2]; va.w = pa[3];
        *(uint4*)&g_A[(size_t)(m0 + row) * KDIM + col] = va;
    }
}

// ---------------- kernel 2: fold weights -> fp16 ----------------
__global__ void fold_kernel(const float* __restrict__ bw,
                            const float* __restrict__ sw,
                            const float* __restrict__ ss) {
    int i = blockIdx.x * blockDim.x + threadIdx.x;    // [tap][n][k]
    if (i >= 9 * 64 * KDIM) return;
    int k = i % KDIM;
    int n = (i / KDIM) & 63;
    int p = i / (KDIM * 64);
    int c = k / 9, g = k % 9;
    int ocp = (n * CIN + c) * 9 + p;
    float val = (g == 0) ? bw[ocp] : sw[ocp * 8 + (g - 1)] * ss[ocp];
    g_B[i] = __float2half(val);
}

// ---------------- kernel 3: fp16 GEMM, swizzled, occ 3, tap-pipelined -----
#define AROWS  258
#define BOFF   (AROWS * 32)              // 8256
#define BTILE  (64 * 32)                 // 2048
#define BUFSZ  (BOFF + 9 * BTILE)        // 26688
#define SMEM_TOT (2 * BUFSZ)             // 53376 -> 3 CTAs/SM

__global__ void __launch_bounds__(256, 3) gemm_kernel(float* __restrict__ out) {
    extern __shared__ __align__(16) char smem[];
    uint32_t sb = smem_u32(smem);
    const int tid  = threadIdx.x;
    const int lane = tid & 31;
    const int wid  = tid >> 5;
    const int mw = wid & 3;
    const int nw = wid >> 2;
    const int m0 = blockIdx.x * MOUT;
    const int k0 = blockIdx.y * KCPER;

    const char* Ap = (const char*)g_A;
    const char* Bp = (const char*)g_B;

    auto prefetch = [&](int kc, uint32_t bb) {
#pragma unroll
        for (int i = 0; i < 7; ++i) {
            int u = tid + i * 256;
            if (u >= 1668) break;
            const char* src;
            uint32_t dst;
            if (u < 516) {
                int row = u >> 1, half = u & 1;
                src = Ap + (size_t)(m0 + row) * (KDIM * 2) + kc * 32 + half * 16;
                dst = bb + row * 32 + ((half ^ ((row >> 2) & 1)) << 4);
            } else {
                int v = u - 516;
                int tile = v >> 7, row = (v >> 1) & 63, half = v & 1;
                src = Bp + (size_t)(tile * 64 + row) * (KDIM * 2) + kc * 32 + half * 16;
                dst = bb + BOFF + tile * BTILE + row * 32
                    + ((half ^ ((row >> 2) & 1)) << 4);
            }
            cp16(dst, src);
        }
    };

    float acc[2][4][4];
#pragma unroll
    for (int b = 0; b < 2; ++b)
#pragma unroll
        for (int c = 0; c < 4; ++c)
#pragma unroll
            for (int d = 0; d < 4; ++d) acc[b][c][d] = 0.0f;

    // --- per-thread swizzled lane offsets ---
    const int ll  = lane & 15;
    const int kh4 = lane >> 4;
    uint32_t aoff[3];
#pragma unroll
    for (int kw = 0; kw < 3; ++kw)
        aoff[kw] = (uint32_t)(ll * 32 + (((((kw + ll) >> 2) & 1) ^ kh4) << 4));
    const int lb  = (lane & 7) + ((lane >> 4) << 3);
    const int khb = (lane >> 3) & 1;
    const uint32_t boff = (uint32_t)(lb * 32 + ((((lb >> 2) & 1) ^ khb) << 4));

    // double-buffered fragments
    uint32_t ah[2][2][4], bf[2][2][4];

    prefetch(k0, sb);
    CP_COMMIT();

    for (int kk = 0; kk < KCPER; ++kk) {
        if (kk < KCPER - 1) prefetch(k0 + kk + 1, sb + ((kk + 1) & 1) * BUFSZ);
        CP_COMMIT();
        CP_WAIT1();
        __syncthreads();

        const uint32_t bb = sb + (kk & 1) * BUFSZ;

        // load tap 0 into buffer 0
        {
#pragma unroll
            for (int t2 = 0; t2 < 2; ++t2)
                LDSM4(ah[0][t2], bb + (uint32_t)((0 * 64 + 0 + mw * 32 + t2 * 16) * 32) + aoff[0]);
#pragma unroll
            for (int nf2 = 0; nf2 < 2; ++nf2)
                LDSM4(bf[0][nf2], bb + BOFF + (uint32_t)(0 * BTILE)
                                  + (uint32_t)((nw * 32 + nf2 * 16) * 32) + boff);
        }

#pragma unroll
        for (int tap = 0; tap < 9; ++tap) {
            const int cur = tap & 1;
            if (tap < 8) {
                const int nt = tap + 1;
                const int nkh = nt / 3, nkw = nt - 3 * (nt / 3);
#pragma unroll
                for (int t2 = 0; t2 < 2; ++t2)
                    LDSM4(ah[cur ^ 1][t2],
                          bb + (uint32_t)((nkh * 64 + nkw + mw * 32 + t2 * 16) * 32) + aoff[nkw]);
#pragma unroll
                for (int nf2 = 0; nf2 < 2; ++nf2)
                    LDSM4(bf[cur ^ 1][nf2],
                          bb + BOFF + (uint32_t)(nt * BTILE)
                             + (uint32_t)((nw * 32 + nf2 * 16) * 32) + boff);
            }
#pragma unroll
            for (int nf2 = 0; nf2 < 2; ++nf2)
#pragma unroll
                for (int hf = 0; hf < 2; ++hf)
#pragma unroll
                    for (int t2 = 0; t2 < 2; ++t2)
                        MMA(acc[t2][nf2 * 2 + hf], ah[cur][t2],
                            bf[cur][nf2][hf * 2], bf[cur][nf2][hf * 2 + 1]);
        }
        __syncthreads();
    }

    // ---- epilogue: atomic accumulate into gmem ----
    const int grp = lane >> 2;
    const int cq  = (lane & 3) * 2;
#pragma unroll
    for (int t2 = 0; t2 < 2; ++t2) {
#pragma unroll
        for (int j2 = 0; j2 < 2; ++j2) {
            int r = mw * 32 + t2 * 16 + grp + j2 * 8;
            int m = m0 + r;
            if (r < MOUT && m < MTOT) {
                int h = (m >> 6) & 63, w = m & 63, b = m >> 12;
                if (h < HO && w < WO) {
                    size_t obase = ((size_t)b * COUT) * (HO * WO) + h * WO + w;
#pragma unroll
                    for (int nf = 0; nf < 4; ++nf) {
                        int o = nw * 32 + nf * 8 + cq;
                        atomicAdd(&out[obase + (size_t)o * (HO * WO)],       acc[t2][nf][j2 * 2]);
                        atomicAdd(&out[obase + (size_t)(o + 1) * (HO * WO)], acc[t2][nf][j2 * 2 + 1]);
                    }
                }
            }
        }
    }
}

// ---------------- launch ----------------
extern "C" void kernel_launch(void* const* d_in, const int* in_sizes, int n_in,
                              void* d_out, int out_size) {
    const float* x  = (const float*)d_in[0];
    const float* bw = (const float*)d_in[1];
    const float* sw = (const float*)d_in[2];
    const float* ss = (const float*)d_in[3];
    float* out = (float*)d_out;

    static int smem_set = 0;
    if (!smem_set) {
        cudaFuncSetAttribute(gemm_kernel, cudaFuncAttributeMaxDynamicSharedMemorySize, SMEM_TOT);
        smem_set = 1;
    }

    int n4 = out_size / 4;
    zero_kernel<<<(n4 + 255) / 256, 256>>>((float4*)out, n4);
    feat_kernel<<<MTOT / 32, 256>>>(x);
    fold_kernel<<<(9 * 64 * KDIM + 255) / 256, 256>>>(bw, sw, ss);
    gemm_kernel<<<dim3(NCTA, NSPLIT), 256, SMEM_TOT>>>(out);
}